// round 1
// baseline (speedup 1.0000x reference)
#include <cuda_runtime.h>

// Shapes are fixed by the problem: x is [8, 4, 1048576] fp32.
constexpr int T_IN  = 1048576;
constexpr int T_OUT = T_IN - 12;       // 1048564, divisible by 4
constexpr int NVEC  = T_OUT / 4;       // 262141 float4 outputs per row
constexpr int ROWS  = 8 * 4;           // 32 independent rows

// Composite 13-tap kernel, computed on device from the runtime fd/gauss inputs.
__device__ float g_comp[16];

__global__ void compute_comp_kernel(const float* __restrict__ fd,
                                    const float* __restrict__ gauss) {
    int k = threadIdx.x;
    if (k < 13) {
        float s = 0.0f;
        #pragma unroll
        for (int i = 0; i < 5; i++) {
            int j = k - i;
            if (j >= 0 && j < 9) s += fd[i] * gauss[j];
        }
        g_comp[k] = s;
    }
}

__global__ __launch_bounds__(256)
void stencil13_kernel(const float* __restrict__ x, float* __restrict__ out) {
    int vt  = blockIdx.x * 256 + threadIdx.x;   // which float4 output in this row
    int row = blockIdx.y;                        // which (b,c) row
    if (vt >= NVEC) return;

    // Load composite coefficients (broadcast; L1/const-cached after first hit)
    float comp[13];
    #pragma unroll
    for (int k = 0; k < 13; k++) comp[k] = g_comp[k];

    long t = 4L * vt;                            // first output index in this row
    const float4* xin = reinterpret_cast<const float4*>(x + (long)row * T_IN + t);

    // 16 consecutive inputs x[t .. t+15]; 16B-aligned (row stride and t are mult of 4)
    float4 a = xin[0];
    float4 b = xin[1];
    float4 c = xin[2];
    float4 d = xin[3];
    float xs[16] = { a.x, a.y, a.z, a.w,
                     b.x, b.y, b.z, b.w,
                     c.x, c.y, c.z, c.w,
                     d.x, d.y, d.z, d.w };

    float4 o;
    float o0 = 0.f, o1 = 0.f, o2 = 0.f, o3 = 0.f;
    #pragma unroll
    for (int k = 0; k < 13; k++) {
        float ck = comp[k];
        o0 = fmaf(ck, xs[k + 0], o0);
        o1 = fmaf(ck, xs[k + 1], o1);
        o2 = fmaf(ck, xs[k + 2], o2);
        o3 = fmaf(ck, xs[k + 3], o3);
    }
    o.x = o0; o.y = o1; o.z = o2; o.w = o3;

    reinterpret_cast<float4*>(out + (long)row * T_OUT)[vt] = o;
}

extern "C" void kernel_launch(void* const* d_in, const int* in_sizes, int n_in,
                              void* d_out, int out_size) {
    const float* x     = (const float*)d_in[0];  // [8,4,1048576] f32
    const float* fd    = (const float*)d_in[1];  // [5]  f32
    const float* gauss = (const float*)d_in[2];  // [9]  f32
    float* out = (float*)d_out;                  // [8,4,1048564] f32

    compute_comp_kernel<<<1, 32>>>(fd, gauss);

    dim3 grid((NVEC + 255) / 256, ROWS);
    stencil13_kernel<<<grid, 256>>>(x, out);
}